// round 1
// baseline (speedup 1.0000x reference)
#include <cuda_runtime.h>
#include <math.h>

#define NMAX 50000
#define DH   256
#define BN_EPS 1e-5f

// ---------------- scratch (device globals; no allocation allowed) ----------
__device__ float g_h [(size_t)NMAX * DH];
__device__ float g_xl[(size_t)NMAX * DH];
__device__ float g_z [(size_t)NMAX * DH];
__device__ float g_deg [NMAX];
__device__ float g_dinv[NMAX];
__device__ float g_bnsum[DH];
__device__ float g_bnsq [DH];
__device__ float g_bnscale[DH];
__device__ float g_bnshift[DH];
__device__ int   g_is64;

// ---------------- edge index access (int32 vs int64 detected at runtime) ---
__device__ __forceinline__ int edge_at(const void* e, long long i, int is64) {
    if (is64) return (int)((const long long*)e)[i];
    return ((const int*)e)[i];
}

// Detect element width: when data is int64 (values < 2^31), every odd int32
// word is zero. Probability of a false positive with real int32 data over
// 1024 samples is ~(1/50000)^1024.
__global__ void k_detect(const int* __restrict__ e, int nwords) {
    if (threadIdx.x == 0 && blockIdx.x == 0) {
        int acc = 0;
        for (int i = 1; i < nwords; i += 2) acc |= e[i];
        g_is64 = (acc == 0) ? 1 : 0;
    }
}

// ---------------- per-launch init: deg=1 (self loops), BN sums = 0 ---------
__global__ void k_init(int N) {
    int i = blockIdx.x * blockDim.x + threadIdx.x;
    if (i < N) g_deg[i] = 1.0f;
    if (i < DH) { g_bnsum[i] = 0.f; g_bnsq[i] = 0.f; }
}

__global__ void k_deg(const void* __restrict__ e, int E) {
    int i = blockIdx.x * blockDim.x + threadIdx.x;
    if (i >= E) return;
    int is64 = g_is64;
    int d = edge_at(e, (long long)E + i, is64);
    atomicAdd(&g_deg[d], 1.0f);
}

__global__ void k_dinv(int N) {
    int i = blockIdx.x * blockDim.x + threadIdx.x;
    if (i < N) g_dinv[i] = rsqrtf(g_deg[i]);
}

// ---------------- generic fp32 GEMM: C[M,256] = A[M,K] @ B[K,256] (+bias) --
// 128x128 tile, 256 threads, 8x8 microtile, K-chunks of 16.
__global__ void k_gemm(const float* __restrict__ A, const float* __restrict__ B,
                       const float* __restrict__ bias, int M, int K, int which) {
    const int N = DH;
    __shared__ float As[16][128];
    __shared__ float Bs[16][128];
    float* C = which ? g_xl : g_h;

    int tid = threadIdx.x;
    int tx = tid & 15, ty = tid >> 4;
    int brow = blockIdx.y * 128, bcol = blockIdx.x * 128;

    float acc[8][8];
#pragma unroll
    for (int i = 0; i < 8; i++)
#pragma unroll
        for (int j = 0; j < 8; j++) acc[i][j] = 0.f;

    for (int k0 = 0; k0 < K; k0 += 16) {
#pragma unroll
        for (int l = 0; l < 2; l++) {
            int idx = tid + l * 256;          // float4 index into 128x16 A tile
            int r = idx >> 2, c4 = idx & 3;
            int grow = brow + r;
            float4 v = make_float4(0.f, 0.f, 0.f, 0.f);
            if (grow < M) v = *(const float4*)(A + (size_t)grow * K + k0 + c4 * 4);
            As[c4 * 4 + 0][r] = v.x; As[c4 * 4 + 1][r] = v.y;
            As[c4 * 4 + 2][r] = v.z; As[c4 * 4 + 3][r] = v.w;
        }
#pragma unroll
        for (int l = 0; l < 2; l++) {
            int idx = tid + l * 256;          // float4 index into 16x128 B tile
            int r = idx >> 5, c4 = idx & 31;
            *(float4*)&Bs[r][c4 * 4] =
                *(const float4*)(B + (size_t)(k0 + r) * N + bcol + c4 * 4);
        }
        __syncthreads();
#pragma unroll
        for (int kk = 0; kk < 16; kk++) {
            float4 a0 = *(float4*)&As[kk][ty * 8], a1 = *(float4*)&As[kk][ty * 8 + 4];
            float4 b0 = *(float4*)&Bs[kk][tx * 8], b1 = *(float4*)&Bs[kk][tx * 8 + 4];
            float a[8] = {a0.x, a0.y, a0.z, a0.w, a1.x, a1.y, a1.z, a1.w};
            float b[8] = {b0.x, b0.y, b0.z, b0.w, b1.x, b1.y, b1.z, b1.w};
#pragma unroll
            for (int i = 0; i < 8; i++)
#pragma unroll
                for (int j = 0; j < 8; j++) acc[i][j] += a[i] * b[j];
        }
        __syncthreads();
    }

#pragma unroll
    for (int i = 0; i < 8; i++) {
        int row = brow + ty * 8 + i;
        if (row >= M) break;
        float* cp = C + (size_t)row * N + bcol + tx * 8;
#pragma unroll
        for (int j = 0; j < 8; j++) {
            float v = acc[i][j];
            if (bias) v += bias[bcol + tx * 8 + j];
            cp[j] = v;
        }
    }
}

// ---------------- z init with self-loop contribution -----------------------
__global__ void k_selfloop(int N) {
    int i = blockIdx.x * blockDim.x + threadIdx.x;
    int total = N * (DH / 4);
    if (i >= total) return;
    int n = i / (DH / 4);
    float w = g_dinv[n]; w *= w;
    float4 v = ((const float4*)g_h)[i];
    v.x *= w; v.y *= w; v.z *= w; v.w *= w;
    ((float4*)g_z)[i] = v;
}

// ---------------- edge scatter: one warp per edge ---------------------------
__global__ void k_scatter(const void* __restrict__ e, int E) {
    int warp = (blockIdx.x * blockDim.x + threadIdx.x) >> 5;
    int lane = threadIdx.x & 31;
    if (warp >= E) return;
    int is64 = g_is64;
    int s = edge_at(e, warp, is64);
    int d = edge_at(e, (long long)E + warp, is64);
    float w = g_dinv[s] * g_dinv[d];
    const float4* hs = (const float4*)(g_h + (size_t)s * DH);
    float* zd = g_z + (size_t)d * DH + lane * 8;
    float4 v0 = hs[lane * 2];
    float4 v1 = hs[lane * 2 + 1];
    atomicAdd(zd + 0, v0.x * w);
    atomicAdd(zd + 1, v0.y * w);
    atomicAdd(zd + 2, v0.z * w);
    atomicAdd(zd + 3, v0.w * w);
    atomicAdd(zd + 4, v1.x * w);
    atomicAdd(zd + 5, v1.y * w);
    atomicAdd(zd + 6, v1.z * w);
    atomicAdd(zd + 7, v1.w * w);
}

// ---------------- z = tanh(z + b_gcn) --------------------------------------
__global__ void k_tanhz(const float* __restrict__ bgcn, int N) {
    int i = blockIdx.x * blockDim.x + threadIdx.x;
    int total = N * (DH / 4);
    if (i >= total) return;
    float4 b = ((const float4*)bgcn)[i & 63];
    float4 v = ((float4*)g_z)[i];
    v.x = tanhf(v.x + b.x);
    v.y = tanhf(v.y + b.y);
    v.z = tanhf(v.z + b.z);
    v.w = tanhf(v.w + b.w);
    ((float4*)g_z)[i] = v;
}

// ---------------- gate GEMM + fused gating/residual/ReLU + BN partials -----
__global__ void k_gate(const float* __restrict__ B, const float* __restrict__ bgate,
                       float* __restrict__ OUT, int M) {
    const int N = DH, K = DH;
    __shared__ float As[16][128];
    __shared__ float Bs[16][128];
    __shared__ float s_sum[128], s_sq[128];
    const float* A = g_z;

    int tid = threadIdx.x;
    int tx = tid & 15, ty = tid >> 4;
    int brow = blockIdx.y * 128, bcol = blockIdx.x * 128;

    if (tid < 128) { s_sum[tid] = 0.f; s_sq[tid] = 0.f; }

    float acc[8][8];
#pragma unroll
    for (int i = 0; i < 8; i++)
#pragma unroll
        for (int j = 0; j < 8; j++) acc[i][j] = 0.f;

    for (int k0 = 0; k0 < K; k0 += 16) {
#pragma unroll
        for (int l = 0; l < 2; l++) {
            int idx = tid + l * 256;
            int r = idx >> 2, c4 = idx & 3;
            int grow = brow + r;
            float4 v = make_float4(0.f, 0.f, 0.f, 0.f);
            if (grow < M) v = *(const float4*)(A + (size_t)grow * K + k0 + c4 * 4);
            As[c4 * 4 + 0][r] = v.x; As[c4 * 4 + 1][r] = v.y;
            As[c4 * 4 + 2][r] = v.z; As[c4 * 4 + 3][r] = v.w;
        }
#pragma unroll
        for (int l = 0; l < 2; l++) {
            int idx = tid + l * 256;
            int r = idx >> 5, c4 = idx & 31;
            *(float4*)&Bs[r][c4 * 4] =
                *(const float4*)(B + (size_t)(k0 + r) * N + bcol + c4 * 4);
        }
        __syncthreads();
#pragma unroll
        for (int kk = 0; kk < 16; kk++) {
            float4 a0 = *(float4*)&As[kk][ty * 8], a1 = *(float4*)&As[kk][ty * 8 + 4];
            float4 b0 = *(float4*)&Bs[kk][tx * 8], b1 = *(float4*)&Bs[kk][tx * 8 + 4];
            float a[8] = {a0.x, a0.y, a0.z, a0.w, a1.x, a1.y, a1.z, a1.w};
            float b[8] = {b0.x, b0.y, b0.z, b0.w, b1.x, b1.y, b1.z, b1.w};
#pragma unroll
            for (int i = 0; i < 8; i++)
#pragma unroll
                for (int j = 0; j < 8; j++) acc[i][j] += a[i] * b[j];
        }
        __syncthreads();
    }

    // epilogue: g = sigmoid(acc + b_gate); out = relu(xl + g*(z - xl)); BN partials
    float csum[8], csq[8];
#pragma unroll
    for (int j = 0; j < 8; j++) { csum[j] = 0.f; csq[j] = 0.f; }

    float bg[8];
#pragma unroll
    for (int j = 0; j < 8; j++) bg[j] = bgate[bcol + tx * 8 + j];

#pragma unroll
    for (int i = 0; i < 8; i++) {
        int row = brow + ty * 8 + i;
        if (row >= M) break;
        const float* zp  = g_z  + (size_t)row * DH + bcol + tx * 8;
        const float* xp  = g_xl + (size_t)row * DH + bcol + tx * 8;
        float*       op  = OUT  + (size_t)row * DH + bcol + tx * 8;
#pragma unroll
        for (int j = 0; j < 8; j++) {
            float gp = acc[i][j] + bg[j];
            float g  = 1.f / (1.f + expf(-gp));
            float zv = zp[j];
            float xv = xp[j];
            float o  = fmaf(g, zv - xv, xv);
            o = fmaxf(o, 0.f);
            op[j] = o;
            csum[j] += o;
            csq[j]  += o * o;
        }
    }
    __syncthreads();   // s_sum/s_sq zeroed before this point
#pragma unroll
    for (int j = 0; j < 8; j++) {
        atomicAdd(&s_sum[tx * 8 + j], csum[j]);
        atomicAdd(&s_sq [tx * 8 + j], csq[j]);
    }
    __syncthreads();
    if (tid < 128) {
        atomicAdd(&g_bnsum[bcol + tid], s_sum[tid]);
        atomicAdd(&g_bnsq [bcol + tid], s_sq[tid]);
    }
}

// ---------------- BN: compute per-column scale/shift, then normalize -------
__global__ void k_bnstats(const float* __restrict__ gamma,
                          const float* __restrict__ beta, int N) {
    int c = threadIdx.x;
    if (c < DH) {
        float invn = 1.0f / (float)N;
        float mu  = g_bnsum[c] * invn;
        float var = g_bnsq[c] * invn - mu * mu;
        float sc  = gamma[c] * rsqrtf(var + BN_EPS);
        g_bnscale[c] = sc;
        g_bnshift[c] = beta[c] - mu * sc;
    }
}

__global__ void k_norm(float* __restrict__ OUT, int N) {
    int i = blockIdx.x * blockDim.x + threadIdx.x;
    int total = N * (DH / 4);
    if (i >= total) return;
    int c4 = i & 63;
    float4 sc = ((const float4*)g_bnscale)[c4];
    float4 sh = ((const float4*)g_bnshift)[c4];
    float4 v = ((float4*)OUT)[i];
    v.x = fmaf(v.x, sc.x, sh.x);
    v.y = fmaf(v.y, sc.y, sh.y);
    v.z = fmaf(v.z, sc.z, sh.z);
    v.w = fmaf(v.w, sc.w, sh.w);
    ((float4*)OUT)[i] = v;
}

// ---------------- launch ----------------------------------------------------
extern "C" void kernel_launch(void* const* d_in, const int* in_sizes, int n_in,
                              void* d_out, int out_size) {
    const float* xs     = (const float*)d_in[0];
    const void*  edges  =               d_in[1];
    const float* W_gcn  = (const float*)d_in[2];
    const float* b_gcn  = (const float*)d_in[3];
    const float* W_lin  = (const float*)d_in[4];
    const float* b_lin  = (const float*)d_in[5];
    const float* W_gate = (const float*)d_in[6];
    const float* b_gate = (const float*)d_in[7];
    const float* gamma  = (const float*)d_in[8];
    const float* beta   = (const float*)d_in[9];
    float* out = (float*)d_out;

    int N = in_sizes[0] / 64;      // 50000
    int E = in_sizes[1] / 2;       // 800000

    int nwords = 2048;
    if (2 * E < nwords) nwords = 2 * E;

    k_detect<<<1, 32>>>((const int*)edges, nwords);
    k_init<<<(N + 255) / 256, 256>>>(N);
    k_deg<<<(E + 255) / 256, 256>>>(edges, E);
    k_dinv<<<(N + 255) / 256, 256>>>(N);

    dim3 g1(2, (N + 127) / 128);
    k_gemm<<<g1, 256>>>(xs, W_gcn, nullptr, N, 64, 0);   // -> g_h
    k_gemm<<<g1, 256>>>(xs, W_lin, b_lin, N, 64, 1);     // -> g_xl

    int total4 = N * (DH / 4);
    k_selfloop<<<(total4 + 255) / 256, 256>>>(N);
    k_scatter<<<(E + 7) / 8, 256>>>(edges, E);
    k_tanhz<<<(total4 + 255) / 256, 256>>>(b_gcn, N);

    k_gate<<<g1, 256>>>(W_gate, b_gate, out, N);

    k_bnstats<<<1, 256>>>(gamma, beta, N);
    k_norm<<<(total4 + 255) / 256, 256>>>(out, N);
}

// round 4
// speedup vs baseline: 4.1934x; 4.1934x over previous
#include <cuda_runtime.h>
#include <math.h>

#define NMAX 50000
#define EMAX 800000
#define DH   256
#define BN_EPS 1e-5f

// ---------------- scratch (device globals; no allocation allowed) ----------
__device__ float g_h [(size_t)NMAX * DH];
__device__ float g_xl[(size_t)NMAX * DH];
__device__ float g_z [(size_t)NMAX * DH];
__device__ int   g_cnt[NMAX];
__device__ int   g_rowstart[NMAX + 1];
__device__ int   g_fill[NMAX];
__device__ int   g_csr_src[EMAX];
__device__ float g_dinv[NMAX];
__device__ float g_bnsum[DH];
__device__ float g_bnsq [DH];
__device__ float g_bnscale[DH];
__device__ float g_bnshift[DH];
__device__ int   g_is64;

// ---------------- edge index access (int32 vs int64 detected at runtime) ---
__device__ __forceinline__ int edge_at(const void* e, long long i, int is64) {
    if (is64) return (int)((const long long*)e)[i];
    return ((const int*)e)[i];
}

// Detect element width: when data is int64 (values < 2^31), every odd int32
// word is zero.
__global__ void k_detect(const int* __restrict__ e, int nwords) {
    if (threadIdx.x == 0 && blockIdx.x == 0) {
        int acc = 0;
        for (int i = 1; i < nwords; i += 2) acc |= e[i];
        g_is64 = (acc == 0) ? 1 : 0;
    }
}

// ---------------- per-launch init: counts=0, BN sums=0 ---------------------
__global__ void k_init(int N) {
    int i = blockIdx.x * blockDim.x + threadIdx.x;
    if (i < N) g_cnt[i] = 0;
    if (i < DH) { g_bnsum[i] = 0.f; g_bnsq[i] = 0.f; }
}

__global__ void k_count(const void* __restrict__ e, int E) {
    int i = blockIdx.x * blockDim.x + threadIdx.x;
    if (i >= E) return;
    int is64 = g_is64;
    int d = edge_at(e, (long long)E + i, is64);
    atomicAdd(&g_cnt[d], 1);
}

// ---------------- single-block exclusive scan over counts ------------------
// Also emits dinv = rsqrt(deg+1) and a second copy of offsets (fill cursors).
__global__ void k_scan(int N) {
    const int T = 1024;
    __shared__ int warpsum[32];
    __shared__ int s_carry;
    int tid = threadIdx.x, lane = tid & 31, wid = tid >> 5;
    if (tid == 0) s_carry = 0;
    __syncthreads();
    for (int base = 0; base < N; base += T) {
        int i = base + tid;
        int v = (i < N) ? g_cnt[i] : 0;
        int x = v;
#pragma unroll
        for (int o = 1; o < 32; o <<= 1) {
            int y = __shfl_up_sync(~0u, x, o);
            if (lane >= o) x += y;
        }
        if (lane == 31) warpsum[wid] = x;
        __syncthreads();
        if (wid == 0) {
            int s = warpsum[lane];
#pragma unroll
            for (int o = 1; o < 32; o <<= 1) {
                int y = __shfl_up_sync(~0u, s, o);
                if (lane >= o) s += y;
            }
            warpsum[lane] = s;
        }
        __syncthreads();
        int incl = x + (wid ? warpsum[wid - 1] : 0);
        int excl = s_carry + incl - v;
        if (i < N) {
            g_rowstart[i] = excl;
            g_fill[i]     = excl;
            g_dinv[i]     = rsqrtf((float)(v + 1));
        }
        __syncthreads();
        if (tid == T - 1) s_carry += incl;
        __syncthreads();
    }
    if (threadIdx.x == 0) g_rowstart[N] = s_carry;
}

__global__ void k_fillcsr(const void* __restrict__ e, int E) {
    int i = blockIdx.x * blockDim.x + threadIdx.x;
    if (i >= E) return;
    int is64 = g_is64;
    int s = edge_at(e, i, is64);
    int d = edge_at(e, (long long)E + i, is64);
    int pos = atomicAdd(&g_fill[d], 1);
    g_csr_src[pos] = s;
}

// ---------------- fp32 GEMM: C[M,256] = A[M,64] @ B[64,256] (+bias) --------
// blockIdx.z selects {W_gcn -> g_h} or {W_lin(+b) -> g_xl}.
__global__ __launch_bounds__(256) void k_gemm2(const float* __restrict__ A,
                       const float* __restrict__ B0, const float* __restrict__ B1,
                       const float* __restrict__ bias1, int M) {
    const int N = DH, K = 64;
    __shared__ float As[16][128];
    __shared__ float Bs[16][128];
    int which = blockIdx.z;
    const float* B = which ? B1 : B0;
    float* C = which ? g_xl : g_h;

    int tid = threadIdx.x;
    int tx = tid & 15, ty = tid >> 4;
    int brow = blockIdx.y * 128, bcol = blockIdx.x * 128;

    float acc[8][8];
#pragma unroll
    for (int i = 0; i < 8; i++)
#pragma unroll
        for (int j = 0; j < 8; j++) acc[i][j] = 0.f;

    for (int k0 = 0; k0 < K; k0 += 16) {
#pragma unroll
        for (int l = 0; l < 2; l++) {
            int idx = tid + l * 256;
            int r = idx >> 2, c4 = idx & 3;
            int grow = brow + r;
            float4 v = make_float4(0.f, 0.f, 0.f, 0.f);
            if (grow < M) v = *(const float4*)(A + (size_t)grow * K + k0 + c4 * 4);
            As[c4 * 4 + 0][r] = v.x; As[c4 * 4 + 1][r] = v.y;
            As[c4 * 4 + 2][r] = v.z; As[c4 * 4 + 3][r] = v.w;
        }
#pragma unroll
        for (int l = 0; l < 2; l++) {
            int idx = tid + l * 256;
            int r = idx >> 5, c4 = idx & 31;
            *(float4*)&Bs[r][c4 * 4] =
                *(const float4*)(B + (size_t)(k0 + r) * N + bcol + c4 * 4);
        }
        __syncthreads();
#pragma unroll
        for (int kk = 0; kk < 16; kk++) {
            float4 a0 = *(float4*)&As[kk][ty * 8], a1 = *(float4*)&As[kk][ty * 8 + 4];
            float4 b0 = *(float4*)&Bs[kk][tx * 8], b1 = *(float4*)&Bs[kk][tx * 8 + 4];
            float a[8] = {a0.x, a0.y, a0.z, a0.w, a1.x, a1.y, a1.z, a1.w};
            float b[8] = {b0.x, b0.y, b0.z, b0.w, b1.x, b1.y, b1.z, b1.w};
#pragma unroll
            for (int i = 0; i < 8; i++)
#pragma unroll
                for (int j = 0; j < 8; j++) acc[i][j] += a[i] * b[j];
        }
        __syncthreads();
    }

#pragma unroll
    for (int i = 0; i < 8; i++) {
        int row = brow + ty * 8 + i;
        if (row >= M) break;
        float* cp = C + (size_t)row * N + bcol + tx * 8;
#pragma unroll
        for (int j = 0; j < 8; j++) {
            float v = acc[i][j];
            if (which) v += bias1[bcol + tx * 8 + j];
            cp[j] = v;
        }
    }
}

// ---------------- CSR gather: warp per node, fused self-loop+bias+tanh -----
// z[n] = tanh( dinv[n] * ( h[n]*dinv[n] + sum_{s in N(n)} h[s]*dinv[s] ) + b )
__global__ __launch_bounds__(256) void k_gather(const float* __restrict__ bgcn, int N) {
    int warp = (blockIdx.x * blockDim.x + threadIdx.x) >> 5;
    int lane = threadIdx.x & 31;
    if (warp >= N) return;
    int n = warp;
    float di = g_dinv[n];

    const float4* hn = (const float4*)(g_h + (size_t)n * DH);
    float4 a0 = hn[lane * 2];
    float4 a1 = hn[lane * 2 + 1];
    a0.x *= di; a0.y *= di; a0.z *= di; a0.w *= di;
    a1.x *= di; a1.y *= di; a1.z *= di; a1.w *= di;

    int e   = g_rowstart[n];
    int end = g_rowstart[n + 1];

    // 4-way unrolled: 4 independent row gathers in flight per iteration
    for (; e + 3 < end; e += 4) {
        int s0 = g_csr_src[e];
        int s1 = g_csr_src[e + 1];
        int s2 = g_csr_src[e + 2];
        int s3 = g_csr_src[e + 3];
        float w0 = g_dinv[s0], w1 = g_dinv[s1];
        float w2 = g_dinv[s2], w3 = g_dinv[s3];
        const float4* h0 = (const float4*)(g_h + (size_t)s0 * DH);
        const float4* h1 = (const float4*)(g_h + (size_t)s1 * DH);
        const float4* h2 = (const float4*)(g_h + (size_t)s2 * DH);
        const float4* h3 = (const float4*)(g_h + (size_t)s3 * DH);
        float4 p0 = h0[lane * 2], p1 = h0[lane * 2 + 1];
        float4 q0 = h1[lane * 2], q1 = h1[lane * 2 + 1];
        float4 r0 = h2[lane * 2], r1 = h2[lane * 2 + 1];
        float4 t0 = h3[lane * 2], t1 = h3[lane * 2 + 1];
        a0.x = fmaf(p0.x, w0, a0.x); a0.y = fmaf(p0.y, w0, a0.y);
        a0.z = fmaf(p0.z, w0, a0.z); a0.w = fmaf(p0.w, w0, a0.w);
        a1.x = fmaf(p1.x, w0, a1.x); a1.y = fmaf(p1.y, w0, a1.y);
        a1.z = fmaf(p1.z, w0, a1.z); a1.w = fmaf(p1.w, w0, a1.w);
        a0.x = fmaf(q0.x, w1, a0.x); a0.y = fmaf(q0.y, w1, a0.y);
        a0.z = fmaf(q0.z, w1, a0.z); a0.w = fmaf(q0.w, w1, a0.w);
        a1.x = fmaf(q1.x, w1, a1.x); a1.y = fmaf(q1.y, w1, a1.y);
        a1.z = fmaf(q1.z, w1, a1.z); a1.w = fmaf(q1.w, w1, a1.w);
        a0.x = fmaf(r0.x, w2, a0.x); a0.y = fmaf(r0.y, w2, a0.y);
        a0.z = fmaf(r0.z, w2, a0.z); a0.w = fmaf(r0.w, w2, a0.w);
        a1.x = fmaf(r1.x, w2, a1.x); a1.y = fmaf(r1.y, w2, a1.y);
        a1.z = fmaf(r1.z, w2, a1.z); a1.w = fmaf(r1.w, w2, a1.w);
        a0.x = fmaf(t0.x, w3, a0.x); a0.y = fmaf(t0.y, w3, a0.y);
        a0.z = fmaf(t0.z, w3, a0.z); a0.w = fmaf(t0.w, w3, a0.w);
        a1.x = fmaf(t1.x, w3, a1.x); a1.y = fmaf(t1.y, w3, a1.y);
        a1.z = fmaf(t1.z, w3, a1.z); a1.w = fmaf(t1.w, w3, a1.w);
    }
    for (; e < end; e++) {
        int s0 = g_csr_src[e];
        float w0 = g_dinv[s0];
        const float4* h0 = (const float4*)(g_h + (size_t)s0 * DH);
        float4 p0 = h0[lane * 2], p1 = h0[lane * 2 + 1];
        a0.x = fmaf(p0.x, w0, a0.x); a0.y = fmaf(p0.y, w0, a0.y);
        a0.z = fmaf(p0.z, w0, a0.z); a0.w = fmaf(p0.w, w0, a0.w);
        a1.x = fmaf(p1.x, w0, a1.x); a1.y = fmaf(p1.y, w0, a1.y);
        a1.z = fmaf(p1.z, w0, a1.z); a1.w = fmaf(p1.w, w0, a1.w);
    }

    float4 b0 = ((const float4*)bgcn)[lane * 2];
    float4 b1 = ((const float4*)bgcn)[lane * 2 + 1];
    float4 o0, o1;
    o0.x = tanhf(fmaf(a0.x, di, b0.x));
    o0.y = tanhf(fmaf(a0.y, di, b0.y));
    o0.z = tanhf(fmaf(a0.z, di, b0.z));
    o0.w = tanhf(fmaf(a0.w, di, b0.w));
    o1.x = tanhf(fmaf(a1.x, di, b1.x));
    o1.y = tanhf(fmaf(a1.y, di, b1.y));
    o1.z = tanhf(fmaf(a1.z, di, b1.z));
    o1.w = tanhf(fmaf(a1.w, di, b1.w));
    float4* zn = (float4*)(g_z + (size_t)n * DH);
    zn[lane * 2]     = o0;
    zn[lane * 2 + 1] = o1;
}

// ---------------- gate GEMM + fused gating/residual/ReLU + BN partials -----
__global__ __launch_bounds__(256) void k_gate(const float* __restrict__ B,
                       const float* __restrict__ bgate,
                       float* __restrict__ OUT, int M) {
    const int N = DH, K = DH;
    __shared__ float As[16][128];
    __shared__ float Bs[16][128];
    __shared__ float s_sum[128], s_sq[128];
    const float* A = g_z;

    int tid = threadIdx.x;
    int tx = tid & 15, ty = tid >> 4;
    int brow = blockIdx.y * 128, bcol = blockIdx.x * 128;

    if (tid < 128) { s_sum[tid] = 0.f; s_sq[tid] = 0.f; }

    float acc[8][8];
#pragma unroll
    for (int i = 0; i < 8; i++)
#pragma unroll
        for (int j = 0; j < 8; j++) acc[i][j] = 0.f;

    for (int k0 = 0; k0 < K; k0 += 16) {
#pragma unroll
        for (int l = 0; l < 2; l++) {
            int idx = tid + l * 256;
            int r = idx >> 2, c4 = idx & 3;
            int grow = brow + r;
            float4 v = make_float4(0.f, 0.f, 0.f, 0.f);
            if (grow < M) v = *(const float4*)(A + (size_t)grow * K + k0 + c4 * 4);
            As[c4 * 4 + 0][r] = v.x; As[c4 * 4 + 1][r] = v.y;
            As[c4 * 4 + 2][r] = v.z; As[c4 * 4 + 3][r] = v.w;
        }
#pragma unroll
        for (int l = 0; l < 2; l++) {
            int idx = tid + l * 256;
            int r = idx >> 5, c4 = idx & 31;
            *(float4*)&Bs[r][c4 * 4] =
                *(const float4*)(B + (size_t)(k0 + r) * N + bcol + c4 * 4);
        }
        __syncthreads();
#pragma unroll
        for (int kk = 0; kk < 16; kk++) {
            float4 a0 = *(float4*)&As[kk][ty * 8], a1 = *(float4*)&As[kk][ty * 8 + 4];
            float4 b0 = *(float4*)&Bs[kk][tx * 8], b1 = *(float4*)&Bs[kk][tx * 8 + 4];
            float a[8] = {a0.x, a0.y, a0.z, a0.w, a1.x, a1.y, a1.z, a1.w};
            float b[8] = {b0.x, b0.y, b0.z, b0.w, b1.x, b1.y, b1.z, b1.w};
#pragma unroll
            for (int i = 0; i < 8; i++)
#pragma unroll
                for (int j = 0; j < 8; j++) acc[i][j] += a[i] * b[j];
        }
        __syncthreads();
    }

    float csum[8], csq[8];
#pragma unroll
    for (int j = 0; j < 8; j++) { csum[j] = 0.f; csq[j] = 0.f; }

    float bg[8];
#pragma unroll
    for (int j = 0; j < 8; j++) bg[j] = bgate[bcol + tx * 8 + j];

#pragma unroll
    for (int i = 0; i < 8; i++) {
        int row = brow + ty * 8 + i;
        if (row >= M) break;
        const float* zp  = g_z  + (size_t)row * DH + bcol + tx * 8;
        const float* xp  = g_xl + (size_t)row * DH + bcol + tx * 8;
        float*       op  = OUT  + (size_t)row * DH + bcol + tx * 8;
#pragma unroll
        for (int j = 0; j < 8; j++) {
            float gp = acc[i][j] + bg[j];
            float g  = 1.f / (1.f + expf(-gp));
            float zv = zp[j];
            float xv = xp[j];
            float o  = fmaf(g, zv - xv, xv);
            o = fmaxf(o, 0.f);
            op[j] = o;
            csum[j] += o;
            csq[j]  += o * o;
        }
    }
    __syncthreads();
#pragma unroll
    for (int j = 0; j < 8; j++) {
        atomicAdd(&s_sum[tx * 8 + j], csum[j]);
        atomicAdd(&s_sq [tx * 8 + j], csq[j]);
    }
    __syncthreads();
    if (tid < 128) {
        atomicAdd(&g_bnsum[bcol + tid], s_sum[tid]);
        atomicAdd(&g_bnsq [bcol + tid], s_sq[tid]);
    }
}

// ---------------- BN: compute per-column scale/shift, then normalize -------
__global__ void k_bnstats(const float* __restrict__ gamma,
                          const float* __restrict__ beta, int N) {
    int c = threadIdx.x;
    if (c < DH) {
        float invn = 1.0f / (float)N;
        float mu  = g_bnsum[c] * invn;
        float var = g_bnsq[c] * invn - mu * mu;
        float sc  = gamma[c] * rsqrtf(var + BN_EPS);
        g_bnscale[c] = sc;
        g_bnshift[c] = beta[c] - mu * sc;
    }
}

__global__ void k_norm(float* __restrict__ OUT, int N) {
    int i = blockIdx.x * blockDim.x + threadIdx.x;
    int total = N * (DH / 4);
    if (i >= total) return;
    int c4 = i & 63;
    float4 sc = ((const float4*)g_bnscale)[c4];
    float4 sh = ((const float4*)g_bnshift)[c4];
    float4 v = ((float4*)OUT)[i];
    v.x = fmaf(v.x, sc.x, sh.x);
    v.y = fmaf(v.y, sc.y, sh.y);
    v.z = fmaf(v.z, sc.z, sh.z);
    v.w = fmaf(v.w, sc.w, sh.w);
    ((float4*)OUT)[i] = v;
}

// ---------------- launch ----------------------------------------------------
extern "C" void kernel_launch(void* const* d_in, const int* in_sizes, int n_in,
                              void* d_out, int out_size) {
    const float* xs     = (const float*)d_in[0];
    const void*  edges  =               d_in[1];
    const float* W_gcn  = (const float*)d_in[2];
    const float* b_gcn  = (const float*)d_in[3];
    const float* W_lin  = (const float*)d_in[4];
    const float* b_lin  = (const float*)d_in[5];
    const float* W_gate = (const float*)d_in[6];
    const float* b_gate = (const float*)d_in[7];
    const float* gamma  = (const float*)d_in[8];
    const float* beta   = (const float*)d_in[9];
    float* out = (float*)d_out;

    int N = in_sizes[0] / 64;      // 50000
    int E = in_sizes[1] / 2;       // 800000

    int nwords = 2048;
    if (2 * E < nwords) nwords = 2 * E;

    k_detect<<<1, 32>>>((const int*)edges, nwords);
    k_init<<<(N + 255) / 256, 256>>>(N);
    k_count<<<(E + 255) / 256, 256>>>(edges, E);
    k_scan<<<1, 1024>>>(N);
    k_fillcsr<<<(E + 255) / 256, 256>>>(edges, E);

    dim3 g2(2, (N + 127) / 128, 2);
    k_gemm2<<<g2, 256>>>(xs, W_gcn, W_lin, b_lin, N);    // -> g_h, g_xl

    k_gather<<<(N + 7) / 8, 256>>>(b_gcn, N);

    dim3 g1(2, (N + 127) / 128);
    k_gate<<<g1, 256>>>(W_gate, b_gate, out, N);

    k_bnstats<<<1, 256>>>(gamma, beta, N);
    k_norm<<<(N * (DH / 4) + 255) / 256, 256>>>(out, N);
}

// round 5
// speedup vs baseline: 6.4947x; 1.5488x over previous
#include <cuda_runtime.h>
#include <math.h>

#define NMAX 50000
#define EMAX 800000
#define DH   256
#define BN_EPS 1e-5f
#define SCAN_CHUNK 1024

// ---------------- scratch (device globals; no allocation allowed) ----------
__device__ float g_h [(size_t)NMAX * DH];
__device__ float g_xl[(size_t)NMAX * DH];
__device__ float g_z [(size_t)NMAX * DH];
__device__ int   g_cnt[NMAX];
__device__ int   g_rowstart[NMAX + 1];
__device__ int   g_fill[NMAX];
__device__ int   g_csr_src[EMAX];
__device__ int   g_blocksum[64];
__device__ int   g_blockoff[64];
__device__ float g_dinv[NMAX];
__device__ float g_bnsum[DH];
__device__ float g_bnsq [DH];
__device__ float g_bnscale[DH];
__device__ float g_bnshift[DH];
__device__ int   g_is64;

// ---------------- helpers ---------------------------------------------------
__device__ __forceinline__ int edge_at(const void* e, long long i, int is64) {
    if (is64) return (int)((const long long*)e)[i];
    return ((const int*)e)[i];
}

__device__ __forceinline__ unsigned f2tf32(float v) {
    unsigned r;
    asm("cvt.rna.tf32.f32 %0, %1;" : "=r"(r) : "f"(v));
    return r;
}

__device__ __forceinline__ void mma_tf32(float* c, const unsigned* a, const unsigned* b) {
    asm volatile(
        "mma.sync.aligned.m16n8k8.row.col.f32.tf32.tf32.f32 "
        "{%0,%1,%2,%3}, {%4,%5,%6,%7}, {%8,%9}, {%0,%1,%2,%3};\n"
        : "+f"(c[0]), "+f"(c[1]), "+f"(c[2]), "+f"(c[3])
        : "r"(a[0]), "r"(a[1]), "r"(a[2]), "r"(a[3]), "r"(b[0]), "r"(b[1]));
}

// Detect element width: int64 data (values < 2^31) has every odd word zero.
__global__ void k_detect(const int* __restrict__ e, int nwords) {
    if (threadIdx.x == 0 && blockIdx.x == 0) {
        int acc = 0;
        for (int i = 1; i < nwords; i += 2) acc |= e[i];
        g_is64 = (acc == 0) ? 1 : 0;
    }
}

__global__ void k_init(int N) {
    int i = blockIdx.x * blockDim.x + threadIdx.x;
    if (i < N) g_cnt[i] = 0;
    if (i < DH) { g_bnsum[i] = 0.f; g_bnsq[i] = 0.f; }
}

__global__ void k_count(const void* __restrict__ e, int E) {
    int i = blockIdx.x * blockDim.x + threadIdx.x;
    if (i >= E) return;
    int is64 = g_is64;
    int d = edge_at(e, (long long)E + i, is64);
    atomicAdd(&g_cnt[d], 1);
}

// ---------------- multi-block scan ------------------------------------------
__global__ void k_scan_p1(int N) {               // per-chunk sums
    __shared__ int wsum[32];
    int b = blockIdx.x, tid = threadIdx.x;
    int i = b * SCAN_CHUNK + tid;
    int v = (i < N) ? g_cnt[i] : 0;
#pragma unroll
    for (int o = 16; o > 0; o >>= 1) v += __shfl_down_sync(~0u, v, o);
    if ((tid & 31) == 0) wsum[tid >> 5] = v;
    __syncthreads();
    if (tid < 32) {
        int s = wsum[tid];
#pragma unroll
        for (int o = 16; o > 0; o >>= 1) s += __shfl_down_sync(~0u, s, o);
        if (tid == 0) g_blocksum[b] = s;
    }
}

__global__ void k_scan_p2(int nb, int N) {       // exclusive scan of chunk sums
    if (threadIdx.x == 0) {
        int acc = 0;
        for (int b = 0; b < nb; b++) {
            g_blockoff[b] = acc;
            acc += g_blocksum[b];
        }
        g_rowstart[N] = acc;
    }
}

__global__ void k_scan_p3(int N) {               // local excl. scan + offset
    __shared__ int wsum[32];
    int b = blockIdx.x, tid = threadIdx.x;
    int lane = tid & 31, wid = tid >> 5;
    int i = b * SCAN_CHUNK + tid;
    int v = (i < N) ? g_cnt[i] : 0;
    int x = v;
#pragma unroll
    for (int o = 1; o < 32; o <<= 1) {
        int y = __shfl_up_sync(~0u, x, o);
        if (lane >= o) x += y;
    }
    if (lane == 31) wsum[wid] = x;
    __syncthreads();
    if (wid == 0) {
        int s = wsum[lane];
#pragma unroll
        for (int o = 1; o < 32; o <<= 1) {
            int y = __shfl_up_sync(~0u, s, o);
            if (lane >= o) s += y;
        }
        wsum[lane] = s;
    }
    __syncthreads();
    int excl = g_blockoff[b] + x - v + (wid ? wsum[wid - 1] : 0);
    if (i < N) {
        g_rowstart[i] = excl;
        g_fill[i]     = excl;
        g_dinv[i]     = rsqrtf((float)(v + 1));
    }
}

__global__ void k_fillcsr(const void* __restrict__ e, int E) {
    int i = blockIdx.x * blockDim.x + threadIdx.x;
    if (i >= E) return;
    int is64 = g_is64;
    int s = edge_at(e, i, is64);
    int d = edge_at(e, (long long)E + i, is64);
    int pos = atomicAdd(&g_fill[d], 1);
    g_csr_src[pos] = s;
}

// ============================================================================
// tf32 tensor-core GEMM: C[M,256] = A[M,K] @ B[K,256]
// 128x128 block tile, 8 warps (2x4), warp tile 64x32 = 4x4 mma(16x8) tiles.
// SMEM operands stored pre-converted to tf32. KC = 32 per chunk.
// ============================================================================
#define PADW 132

// ---- pass 1: both input GEMMs (blockIdx.z: 0 -> g_h, 1 -> g_xl(+bias)) ----
__global__ __launch_bounds__(256) void k_gemm_tf32(
        const float* __restrict__ A,
        const float* __restrict__ B0, const float* __restrict__ B1,
        const float* __restrict__ bias1, int M) {
    __shared__ unsigned As[32][PADW];
    __shared__ unsigned Bs[32][PADW];
    const int K = 64;
    int which = blockIdx.z;
    const float* B = which ? B1 : B0;
    float* C = which ? g_xl : g_h;

    int tid = threadIdx.x;
    int wid = tid >> 5, lane = tid & 31;
    int g = lane >> 2, tig = lane & 3;
    int warp_m = wid & 1, warp_n = wid >> 1;
    int brow = blockIdx.y * 128, bcol = blockIdx.x * 128;

    float acc[4][4][4];
#pragma unroll
    for (int mt = 0; mt < 4; mt++)
#pragma unroll
        for (int nt = 0; nt < 4; nt++)
#pragma unroll
            for (int r = 0; r < 4; r++) acc[mt][nt][r] = 0.f;

    for (int k0 = 0; k0 < K; k0 += 32) {
#pragma unroll
        for (int l = 0; l < 4; l++) {          // A: 1024 float4 slots
            int s = tid + l * 256;
            int m = s >> 3, kq = s & 7;
            float4 v = make_float4(0.f, 0.f, 0.f, 0.f);
            if (brow + m < M)
                v = *(const float4*)(A + (size_t)(brow + m) * K + k0 + kq * 4);
            As[kq * 4 + 0][m] = f2tf32(v.x);
            As[kq * 4 + 1][m] = f2tf32(v.y);
            As[kq * 4 + 2][m] = f2tf32(v.z);
            As[kq * 4 + 3][m] = f2tf32(v.w);
        }
#pragma unroll
        for (int l = 0; l < 4; l++) {          // B: 1024 float4 slots
            int s = tid + l * 256;
            int k = s >> 5, nq = s & 31;
            float4 v = *(const float4*)(B + (size_t)(k0 + k) * DH + bcol + nq * 4);
            Bs[k][nq * 4 + 0] = f2tf32(v.x);
            Bs[k][nq * 4 + 1] = f2tf32(v.y);
            Bs[k][nq * 4 + 2] = f2tf32(v.z);
            Bs[k][nq * 4 + 3] = f2tf32(v.w);
        }
        __syncthreads();
#pragma unroll
        for (int kk = 0; kk < 32; kk += 8) {
            unsigned af[4][4], bf[4][2];
#pragma unroll
            for (int mt = 0; mt < 4; mt++) {
                int mb = warp_m * 64 + mt * 16 + g;
                af[mt][0] = As[kk + tig    ][mb];
                af[mt][1] = As[kk + tig    ][mb + 8];
                af[mt][2] = As[kk + tig + 4][mb];
                af[mt][3] = As[kk + tig + 4][mb + 8];
            }
#pragma unroll
            for (int nt = 0; nt < 4; nt++) {
                int nb = warp_n * 32 + nt * 8 + g;
                bf[nt][0] = Bs[kk + tig    ][nb];
                bf[nt][1] = Bs[kk + tig + 4][nb];
            }
#pragma unroll
            for (int mt = 0; mt < 4; mt++)
#pragma unroll
                for (int nt = 0; nt < 4; nt++)
                    mma_tf32(acc[mt][nt], af[mt], bf[nt]);
        }
        __syncthreads();
    }

#pragma unroll
    for (int mt = 0; mt < 4; mt++) {
        int row = brow + warp_m * 64 + mt * 16 + g;
#pragma unroll
        for (int nt = 0; nt < 4; nt++) {
            int col = bcol + warp_n * 32 + nt * 8 + 2 * tig;
            float bx = 0.f, by = 0.f;
            if (which) { bx = bias1[col]; by = bias1[col + 1]; }
            if (row < M) {
                float2 v = make_float2(acc[mt][nt][0] + bx, acc[mt][nt][1] + by);
                *(float2*)(C + (size_t)row * DH + col) = v;
            }
            if (row + 8 < M) {
                float2 v = make_float2(acc[mt][nt][2] + bx, acc[mt][nt][3] + by);
                *(float2*)(C + (size_t)(row + 8) * DH + col) = v;
            }
        }
    }
}

// ---- pass 2: gate GEMM (z @ W_gate) + fused sigmoid/residual/ReLU + BN ----
__global__ __launch_bounds__(256) void k_gate_tf32(
        const float* __restrict__ B, const float* __restrict__ bgate,
        float* __restrict__ OUT, int M) {
    __shared__ unsigned As[32][PADW];
    __shared__ unsigned Bs[32][PADW];
    __shared__ float s_sum[128], s_sq[128];
    const int K = DH;
    const float* A = g_z;

    int tid = threadIdx.x;
    int wid = tid >> 5, lane = tid & 31;
    int g = lane >> 2, tig = lane & 3;
    int warp_m = wid & 1, warp_n = wid >> 1;
    int brow = blockIdx.y * 128, bcol = blockIdx.x * 128;

    if (tid < 128) { s_sum[tid] = 0.f; s_sq[tid] = 0.f; }

    float acc[4][4][4];
#pragma unroll
    for (int mt = 0; mt < 4; mt++)
#pragma unroll
        for (int nt = 0; nt < 4; nt++)
#pragma unroll
            for (int r = 0; r < 4; r++) acc[mt][nt][r] = 0.f;

    for (int k0 = 0; k0 < K; k0 += 32) {
#pragma unroll
        for (int l = 0; l < 4; l++) {
            int s = tid + l * 256;
            int m = s >> 3, kq = s & 7;
            float4 v = make_float4(0.f, 0.f, 0.f, 0.f);
            if (brow + m < M)
                v = *(const float4*)(A + (size_t)(brow + m) * K + k0 + kq * 4);
            As[kq * 4 + 0][m] = f2tf32(v.x);
            As[kq * 4 + 1][m] = f2tf32(v.y);
            As[kq * 4 + 2][m] = f2tf32(v.z);
            As[kq * 4 + 3][m] = f2tf32(v.w);
        }
#pragma unroll
        for (int l = 0; l < 4; l++) {
            int s = tid + l * 256;
            int k = s >> 5, nq = s & 31;
            float4 v = *(const float4*)(B + (size_t)(k0 + k) * DH + bcol + nq * 4);
            Bs[k][nq * 4 + 0] = f2tf32(v.x);
            Bs[k][nq * 4 + 1] = f2tf32(v.y);
            Bs[k][nq * 4 + 2] = f2tf32(v.z);
            Bs[k][nq * 4 + 3] = f2tf32(v.w);
        }
        __syncthreads();
#pragma unroll
        for (int kk = 0; kk < 32; kk += 8) {
            unsigned af[4][4], bf[4][2];
#pragma unroll
            for (int mt = 0; mt < 4; mt++) {
                int mb = warp_m * 64 + mt * 16 + g;
                af[mt][0] = As[kk + tig    ][mb];
                af[mt][1] = As[kk + tig    ][mb + 8];
                af[mt][2] = As[kk + tig + 4][mb];
                af[mt][3] = As[kk + tig + 4][mb + 8];
            }
#pragma unroll
            for (int nt = 0; nt < 4; nt++) {
                int nb = warp_n * 32 + nt * 8 + g;
                bf[nt][0] = Bs[kk + tig    ][nb];
                bf[nt][1] = Bs[kk + tig + 4][nb];
            }
#pragma unroll
            for (int mt = 0; mt < 4; mt++)
#pragma unroll
                for (int nt = 0; nt < 4; nt++)
                    mma_tf32(acc[mt][nt], af[mt], bf[nt]);
        }
        __syncthreads();
    }

    // epilogue: g=sigmoid(acc+bg); out=relu(xl+g*(z-xl)); BN partial sums
    float csum[4][2], csq[4][2];
#pragma unroll
    for (int nt = 0; nt < 4; nt++) {
        csum[nt][0] = 0.f; csum[nt][1] = 0.f;
        csq [nt][0] = 0.f; csq [nt][1] = 0.f;
    }

#pragma unroll
    for (int mt = 0; mt < 4; mt++) {
#pragma unroll
        for (int half = 0; half < 2; half++) {
            int row = brow + warp_m * 64 + mt * 16 + g + half * 8;
            if (row >= M) continue;
#pragma unroll
            for (int nt = 0; nt < 4; nt++) {
                int col = bcol + warp_n * 32 + nt * 8 + 2 * tig;
                const float* zp = g_z  + (size_t)row * DH + col;
                const float* xp = g_xl + (size_t)row * DH + col;
                float*       op = OUT  + (size_t)row * DH + col;
                float2 zv = *(const float2*)zp;
                float2 xv = *(const float2*)xp;
#pragma unroll
                for (int c = 0; c < 2; c++) {
                    float gp = acc[mt][nt][half * 2 + c] + bgate[col + c];
                    float gg = 1.f / (1.f + expf(-gp));
                    float zz = c ? zv.y : zv.x;
                    float xx = c ? xv.y : xv.x;
                    float o = fmaf(gg, zz - xx, xx);
                    o = fmaxf(o, 0.f);
                    op[c] = o;
                    csum[nt][c] += o;
                    csq [nt][c] += o * o;
                }
            }
        }
    }
#pragma unroll
    for (int nt = 0; nt < 4; nt++) {
        int cl = warp_n * 32 + nt * 8 + 2 * tig;
        atomicAdd(&s_sum[cl],     csum[nt][0]);
        atomicAdd(&s_sum[cl + 1], csum[nt][1]);
        atomicAdd(&s_sq [cl],     csq [nt][0]);
        atomicAdd(&s_sq [cl + 1], csq [nt][1]);
    }
    __syncthreads();
    if (tid < 128) {
        atomicAdd(&g_bnsum[bcol + tid], s_sum[tid]);
        atomicAdd(&g_bnsq [bcol + tid], s_sq [tid]);
    }
}

// ---------------- CSR gather: warp per node, fused self-loop+bias+tanh -----
__global__ __launch_bounds__(256) void k_gather(const float* __restrict__ bgcn, int N) {
    int warp = (blockIdx.x * blockDim.x + threadIdx.x) >> 5;
    int lane = threadIdx.x & 31;
    if (warp >= N) return;
    int n = warp;
    float di = g_dinv[n];

    const float4* hn = (const float4*)(g_h + (size_t)n * DH);
    float4 a0 = hn[lane * 2];
    float4 a1 = hn[lane * 2 + 1];
    a0.x *= di; a0.y *= di; a0.z *= di; a0.w *= di;
    a1.x *= di; a1.y *= di; a1.z *= di; a1.w *= di;

    int e   = g_rowstart[n];
    int end = g_rowstart[n + 1];

    for (; e + 3 < end; e += 4) {
        int s0 = g_csr_src[e];
        int s1 = g_csr_src[e + 1];
        int s2 = g_csr_src[e + 2];
        int s3 = g_csr_src[e + 3];
        float w0 = g_dinv[s0], w1 = g_dinv[s1];
        float w2 = g_dinv[s2], w3 = g_dinv[s3];
        const float4* h0 = (const float4*)(g_h + (size_t)s0 * DH);
        const float4* h1 = (const float4*)(g_h + (size_t)s1 * DH);
        const float4* h2 = (const float4*)(g_h + (size_t)s2 * DH);
        const float4* h3 = (const float4*)(g_h + (size_t)s3 * DH);
        float4 p0 = h0[lane * 2], p1 = h0[lane * 2 + 1];
        float4 q0 = h1[lane * 2], q1 = h1[lane * 2 + 1];
        float4 r0 = h2[lane * 2], r1 = h2[lane * 2 + 1];
        float4 t0 = h3[lane * 2], t1 = h3[lane * 2 + 1];
        a0.x = fmaf(p0.x, w0, a0.x); a0.y = fmaf(p0.y, w0, a0.y);
        a0.z = fmaf(p0.z, w0, a0.z); a0.w = fmaf(p0.w, w0, a0.w);
        a1.x = fmaf(p1.x, w0, a1.x); a1.y = fmaf(p1.y, w0, a1.y);
        a1.z = fmaf(p1.z, w0, a1.z); a1.w = fmaf(p1.w, w0, a1.w);
        a0.x = fmaf(q0.x, w1, a0.x); a0.y = fmaf(q0.y, w1, a0.y);
        a0.z = fmaf(q0.z, w1, a0.z); a0.w = fmaf(q0.w, w1, a0.w);
        a1.x = fmaf(q1.x, w1, a1.x); a1.y = fmaf(q1.y, w1, a1.y);
        a1.z = fmaf(q1.z, w1, a1.z); a1.w = fmaf(q1.w, w1, a1.w);
        a0.x = fmaf(r0.x, w2, a0.x); a0.y = fmaf(r0.y, w2, a0.y);
        a0.z = fmaf(r0.z, w2, a0.z); a0.w = fmaf(r0.w, w2, a0.w);
        a1.x = fmaf(r1.x, w2, a1.x); a1.y = fmaf(r1.y, w2, a1.y);
        a1.z = fmaf(r1.z, w2, a1.z); a1.w = fmaf(r1.w, w2, a1.w);
        a0.x = fmaf(t0.x, w3, a0.x); a0.y = fmaf(t0.y, w3, a0.y);
        a0.z = fmaf(t0.z, w3, a0.z); a0.w = fmaf(t0.w, w3, a0.w);
        a1.x = fmaf(t1.x, w3, a1.x); a1.y = fmaf(t1.y, w3, a1.y);
        a1.z = fmaf(t1.z, w3, a1.z); a1.w = fmaf(t1.w, w3, a1.w);
    }
    for (; e < end; e++) {
        int s0 = g_csr_src[e];
        float w0 = g_dinv[s0];
        const float4* h0 = (const float4*)(g_h + (size_t)s0 * DH);
        float4 p0 = h0[lane * 2], p1 = h0[lane * 2 + 1];
        a0.x = fmaf(p0.x, w0, a0.x); a0.y = fmaf(p0.y, w0, a0.y);
        a0.z = fmaf(p0.z, w0, a0.z); a0.w = fmaf(p0.w, w0, a0.w);
        a1.x = fmaf(p1.x, w0, a1.x); a1.y = fmaf(p1.y, w0, a1.y);
        a1.z = fmaf(p1.z, w0, a1.z); a1.w = fmaf(p1.w, w0, a1.w);
    }

    float4 b0 = ((const float4*)bgcn)[lane * 2];
    float4 b1 = ((const float4*)bgcn)[lane * 2 + 1];
    float4 o0, o1;
    o0.x = tanhf(fmaf(a0.x, di, b0.x));
    o0.y = tanhf(fmaf(a0.y, di, b0.y));
    o0.z = tanhf(fmaf(a0.z, di, b0.z));
    o0.w = tanhf(fmaf(a0.w, di, b0.w));
    o1.x = tanhf(fmaf(a1.x, di, b1.x));
    o1.y = tanhf(fmaf(a1.y, di, b1.y));
    o1.z = tanhf(fmaf(a1.z, di, b1.z));
    o1.w = tanhf(fmaf(a1.w, di, b1.w));
    float4* zn = (float4*)(g_z + (size_t)n * DH);
    zn[lane * 2]     = o0;
    zn[lane * 2 + 1] = o1;
}

// ---------------- BN finalize ----------------------------------------------
__global__ void k_bnstats(const float* __restrict__ gamma,
                          const float* __restrict__ beta, int N) {
    int c = threadIdx.x;
    if (c < DH) {
        float invn = 1.0f / (float)N;
        float mu  = g_bnsum[c] * invn;
        float var = g_bnsq[c] * invn - mu * mu;
        float sc  = gamma[c] * rsqrtf(var + BN_EPS);
        g_bnscale[c] = sc;
        g_bnshift[c] = beta[c] - mu * sc;
    }
}

__global__ void k_norm(float* __restrict__ OUT, int N) {
    int i = blockIdx.x * blockDim.x + threadIdx.x;
    int total = N * (DH / 4);
    if (i >= total) return;
    int c4 = i & 63;
    float4 sc = ((const float4*)g_bnscale)[c4];
    float4 sh = ((const float4*)g_bnshift)[c4];
    float4 v = ((float4*)OUT)[i];
    v.x = fmaf(v.x, sc.x, sh.x);
    v.y = fmaf(v.y, sc.y, sh.y);
    v.z = fmaf(v.z, sc.z, sh.z);
    v.w = fmaf(v.w, sc.w, sh.w);
    ((float4*)OUT)[i] = v;
}

// ---------------- launch ----------------------------------------------------
extern "C" void kernel_launch(void* const* d_in, const int* in_sizes, int n_in,
                              void* d_out, int out_size) {
    const float* xs     = (const float*)d_in[0];
    const void*  edges  =               d_in[1];
    const float* W_gcn  = (const float*)d_in[2];
    const float* b_gcn  = (const float*)d_in[3];
    const float* W_lin  = (const float*)d_in[4];
    const float* b_lin  = (const float*)d_in[5];
    const float* W_gate = (const float*)d_in[6];
    const float* b_gate = (const float*)d_in[7];
    const float* gamma  = (const float*)d_in[8];
    const float* beta   = (const float*)d_in[9];
    float* out = (float*)d_out;

    int N = in_sizes[0] / 64;      // 50000
    int E = in_sizes[1] / 2;       // 800000

    int nwords = 2048;
    if (2 * E < nwords) nwords = 2 * E;

    int nb = (N + SCAN_CHUNK - 1) / SCAN_CHUNK;

    k_detect<<<1, 32>>>((const int*)edges, nwords);
    k_init<<<(N + 255) / 256, 256>>>(N);
    k_count<<<(E + 255) / 256, 256>>>(edges, E);
    k_scan_p1<<<nb, SCAN_CHUNK>>>(N);
    k_scan_p2<<<1, 32>>>(nb, N);
    k_scan_p3<<<nb, SCAN_CHUNK>>>(N);
    k_fillcsr<<<(E + 255) / 256, 256>>>(edges, E);

    dim3 g2(2, (N + 127) / 128, 2);
    k_gemm_tf32<<<g2, 256>>>(xs, W_gcn, W_lin, b_lin, N);   // -> g_h, g_xl

    k_gather<<<(N + 7) / 8, 256>>>(b_gcn, N);

    dim3 g1(2, (N + 127) / 128);
    k_gate_tf32<<<g1, 256>>>(W_gate, b_gate, out, N);

    k_bnstats<<<1, 256>>>(gamma, beta, N);
    k_norm<<<(N * (DH / 4) + 255) / 256, 256>>>(out, N);
}

// round 8
// speedup vs baseline: 8.3655x; 1.2880x over previous
#include <cuda_runtime.h>
#include <math.h>

#define NMAX 50000
#define EMAX 800000
#define DIN  64
#define DH   256
#define BN_EPS 1e-5f
#define SCAN_CHUNK 1024

// ---------------- scratch (device globals; no allocation allowed) ----------
__device__ float g_agg[(size_t)NMAX * DIN];   // aggregated xs (pre-projection)
__device__ float g_xl [(size_t)NMAX * DH];
__device__ float g_z  [(size_t)NMAX * DH];
__device__ int   g_cnt[NMAX];
__device__ int   g_rowstart[NMAX + 1];
__device__ int   g_fill[NMAX];
__device__ int   g_csr_src[EMAX];
__device__ int   g_blocksum[64];
__device__ int   g_blockoff[64];
__device__ float g_dinv[NMAX];
__device__ float g_bnsum[DH];
__device__ float g_bnsq [DH];
__device__ float g_bnscale[DH];
__device__ float g_bnshift[DH];
__device__ int   g_is64;

// ---------------- helpers ---------------------------------------------------
__device__ __forceinline__ int edge_at(const void* e, long long i, int is64) {
    if (is64) return (int)((const long long*)e)[i];
    return ((const int*)e)[i];
}

__device__ __forceinline__ unsigned f2tf32(float v) {
    unsigned r;
    asm("cvt.rna.tf32.f32 %0, %1;" : "=r"(r) : "f"(v));
    return r;
}

__device__ __forceinline__ void mma_tf32(float* c, const unsigned* a, const unsigned* b) {
    asm volatile(
        "mma.sync.aligned.m16n8k8.row.col.f32.tf32.tf32.f32 "
        "{%0,%1,%2,%3}, {%4,%5,%6,%7}, {%8,%9}, {%0,%1,%2,%3};\n"
        : "+f"(c[0]), "+f"(c[1]), "+f"(c[2]), "+f"(c[3])
        : "r"(a[0]), "r"(a[1]), "r"(a[2]), "r"(a[3]), "r"(b[0]), "r"(b[1]));
}

// Detect element width: int64 data (values < 2^31) has every odd word zero.
__global__ void k_detect(const int* __restrict__ e, int nwords) {
    int lane = threadIdx.x;
    int acc = 0;
    for (int i = 1 + 2 * lane; i < nwords; i += 64) acc |= e[i];
#pragma unroll
    for (int o = 16; o > 0; o >>= 1) acc |= __shfl_down_sync(~0u, acc, o);
    if (lane == 0) g_is64 = (acc == 0) ? 1 : 0;
}

__global__ void k_init(int N) {
    int i = blockIdx.x * blockDim.x + threadIdx.x;
    if (i < N) g_cnt[i] = 0;
    if (i < DH) { g_bnsum[i] = 0.f; g_bnsq[i] = 0.f; }
}

__global__ void k_count(const void* __restrict__ e, int E) {
    int i = blockIdx.x * blockDim.x + threadIdx.x;
    if (i >= E) return;
    int is64 = g_is64;
    int d = edge_at(e, (long long)E + i, is64);
    atomicAdd(&g_cnt[d], 1);
}

// ---------------- multi-block scan ------------------------------------------
__global__ void k_scan_p1(int N) {               // per-chunk sums
    __shared__ int wsum[32];
    int b = blockIdx.x, tid = threadIdx.x;
    int i = b * SCAN_CHUNK + tid;
    int v = (i < N) ? g_cnt[i] : 0;
#pragma unroll
    for (int o = 16; o > 0; o >>= 1) v += __shfl_down_sync(~0u, v, o);
    if ((tid & 31) == 0) wsum[tid >> 5] = v;
    __syncthreads();
    if (tid < 32) {
        int s = wsum[tid];
#pragma unroll
        for (int o = 16; o > 0; o >>= 1) s += __shfl_down_sync(~0u, s, o);
        if (tid == 0) g_blocksum[b] = s;
    }
}

__global__ void k_scan_p2(int nb, int N) {       // exclusive scan of chunk sums
    if (threadIdx.x == 0) {
        int acc = 0;
        for (int b = 0; b < nb; b++) {
            g_blockoff[b] = acc;
            acc += g_blocksum[b];
        }
        g_rowstart[N] = acc;
    }
}

__global__ void k_scan_p3(int N) {               // local excl. scan + offset
    __shared__ int wsum[32];
    int b = blockIdx.x, tid = threadIdx.x;
    int lane = tid & 31, wid = tid >> 5;
    int i = b * SCAN_CHUNK + tid;
    int v = (i < N) ? g_cnt[i] : 0;
    int x = v;
#pragma unroll
    for (int o = 1; o < 32; o <<= 1) {
        int y = __shfl_up_sync(~0u, x, o);
        if (lane >= o) x += y;
    }
    if (lane == 31) wsum[wid] = x;
    __syncthreads();
    if (wid == 0) {
        int s = wsum[lane];
#pragma unroll
        for (int o = 1; o < 32; o <<= 1) {
            int y = __shfl_up_sync(~0u, s, o);
            if (lane >= o) s += y;
        }
        wsum[lane] = s;
    }
    __syncthreads();
    int excl = g_blockoff[b] + x - v + (wid ? wsum[wid - 1] : 0);
    if (i < N) {
        g_rowstart[i] = excl;
        g_fill[i]     = excl;
        g_dinv[i]     = rsqrtf((float)(v + 1));
    }
}

__global__ void k_fillcsr(const void* __restrict__ e, int E) {
    int i = blockIdx.x * blockDim.x + threadIdx.x;
    if (i >= E) return;
    int is64 = g_is64;
    int s = edge_at(e, i, is64);
    int d = edge_at(e, (long long)E + i, is64);
    int pos = atomicAdd(&g_fill[d], 1);
    g_csr_src[pos] = s;
}

// ---------------- xs aggregation: warp per node, float2 per lane ------------
// agg[n] = dinv[n] * ( dinv[n]*xs[n] + sum_{s in N(n)} dinv[s]*xs[s] )
__global__ __launch_bounds__(256) void k_gatherx(const float* __restrict__ xs, int N) {
    int warp = (blockIdx.x * blockDim.x + threadIdx.x) >> 5;
    int lane = threadIdx.x & 31;
    if (warp >= N) return;
    int n = warp;
    float di = g_dinv[n];

    float2 a = ((const float2*)(xs + (size_t)n * DIN))[lane];
    a.x *= di; a.y *= di;

    int e   = g_rowstart[n];
    int end = g_rowstart[n + 1];

    for (; e + 7 < end; e += 8) {
        int   si[8];
        float wi[8];
        float2 vi[8];
#pragma unroll
        for (int u = 0; u < 8; u++) si[u] = g_csr_src[e + u];
#pragma unroll
        for (int u = 0; u < 8; u++) wi[u] = g_dinv[si[u]];
#pragma unroll
        for (int u = 0; u < 8; u++)
            vi[u] = ((const float2*)(xs + (size_t)si[u] * DIN))[lane];
#pragma unroll
        for (int u = 0; u < 8; u++) {
            a.x = fmaf(vi[u].x, wi[u], a.x);
            a.y = fmaf(vi[u].y, wi[u], a.y);
        }
    }
    for (; e < end; e++) {
        int s = g_csr_src[e];
        float w = g_dinv[s];
        float2 v = ((const float2*)(xs + (size_t)s * DIN))[lane];
        a.x = fmaf(v.x, w, a.x);
        a.y = fmaf(v.y, w, a.y);
    }
    a.x *= di; a.y *= di;
    ((float2*)(g_agg + (size_t)n * DIN))[lane] = a;
}

// ============================================================================
// tf32 tensor-core GEMM: C[M,256] = A[M,K] @ B[K,256]
// 128x128 block tile, 8 warps (2x4), warp tile 64x32 = 4x4 mma(16x8) tiles.
// ============================================================================
#define PADW 132

// ---- pass 1: blockIdx.z==0: tanh(agg@W_gcn + b_gcn) -> g_z
//              blockIdx.z==1: xs@W_lin + b_lin        -> g_xl
__global__ __launch_bounds__(256) void k_gemm_tf32(
        const float* __restrict__ A1,
        const float* __restrict__ B0, const float* __restrict__ B1,
        const float* __restrict__ bias0, const float* __restrict__ bias1, int M) {
    __shared__ unsigned As[32][PADW];
    __shared__ unsigned Bs[32][PADW];
    const int K = DIN;
    int which = blockIdx.z;
    const float* A = which ? A1 : g_agg;
    const float* B = which ? B1 : B0;
    const float* bias = which ? bias1 : bias0;
    float* C = which ? g_xl : g_z;

    int tid = threadIdx.x;
    int wid = tid >> 5, lane = tid & 31;
    int g = lane >> 2, tig = lane & 3;
    int warp_m = wid & 1, warp_n = wid >> 1;
    int brow = blockIdx.y * 128, bcol = blockIdx.x * 128;

    float acc[4][4][4];
#pragma unroll
    for (int mt = 0; mt < 4; mt++)
#pragma unroll
        for (int nt = 0; nt < 4; nt++)
#pragma unroll
            for (int r = 0; r < 4; r++) acc[mt][nt][r] = 0.f;

    for (int k0 = 0; k0 < K; k0 += 32) {
#pragma unroll
        for (int l = 0; l < 4; l++) {          // A: 1024 float4 slots
            int s = tid + l * 256;
            int m = s >> 3, kq = s & 7;
            float4 v = make_float4(0.f, 0.f, 0.f, 0.f);
            if (brow + m < M)
                v = *(const float4*)(A + (size_t)(brow + m) * K + k0 + kq * 4);
            As[kq * 4 + 0][m] = f2tf32(v.x);
            As[kq * 4 + 1][m] = f2tf32(v.y);
            As[kq * 4 + 2][m] = f2tf32(v.z);
            As[kq * 4 + 3][m] = f2tf32(v.w);
        }
#pragma unroll
        for (int l = 0; l < 4; l++) {          // B: 1024 float4 slots
            int s = tid + l * 256;
            int k = s >> 5, nq = s & 31;
            float4 v = *(const float4*)(B + (size_t)(k0 + k) * DH + bcol + nq * 4);
            Bs[k][nq * 4 + 0] = f2tf32(v.x);
            Bs[k][nq * 4 + 1] = f2tf32(v.y);
            Bs[k][nq * 4 + 2] = f2tf32(v.z);
            Bs[k][nq * 4 + 3] = f2tf32(v.w);
        }
        __syncthreads();
#pragma unroll
        for (int kk = 0; kk < 32; kk += 8) {
            unsigned af[4][4], bf[4][2];
#pragma unroll
            for (int mt = 0; mt < 4; mt++) {
                int mb = warp_m * 64 + mt * 16 + g;
                af[mt][0] = As[kk + tig    ][mb];
                af[mt][1] = As[kk + tig    ][mb + 8];
                af[mt][2] = As[kk + tig + 4][mb];
                af[mt][3] = As[kk + tig + 4][mb + 8];
            }
#pragma unroll
            for (int nt = 0; nt < 4; nt++) {
                int nb = warp_n * 32 + nt * 8 + g;
                bf[nt][0] = Bs[kk + tig    ][nb];
                bf[nt][1] = Bs[kk + tig + 4][nb];
            }
#pragma unroll
            for (int mt = 0; mt < 4; mt++)
#pragma unroll
                for (int nt = 0; nt < 4; nt++)
                    mma_tf32(acc[mt][nt], af[mt], bf[nt]);
        }
        __syncthreads();
    }

#pragma unroll
    for (int mt = 0; mt < 4; mt++) {
        int row = brow + warp_m * 64 + mt * 16 + g;
#pragma unroll
        for (int nt = 0; nt < 4; nt++) {
            int col = bcol + warp_n * 32 + nt * 8 + 2 * tig;
            float bx = bias[col], by = bias[col + 1];
            if (row < M) {
                float vx = acc[mt][nt][0] + bx, vy = acc[mt][nt][1] + by;
                if (!which) { vx = tanhf(vx); vy = tanhf(vy); }
                *(float2*)(C + (size_t)row * DH + col) = make_float2(vx, vy);
            }
            if (row + 8 < M) {
                float vx = acc[mt][nt][2] + bx, vy = acc[mt][nt][3] + by;
                if (!which) { vx = tanhf(vx); vy = tanhf(vy); }
                *(float2*)(C + (size_t)(row + 8) * DH + col) = make_float2(vx, vy);
            }
        }
    }
}

// ---- pass 2: gate GEMM (z @ W_gate) + fused sigmoid/residual/ReLU + BN ----
__global__ __launch_bounds__(256) void k_gate_tf32(
        const float* __restrict__ B, const float* __restrict__ bgate,
        float* __restrict__ OUT, int M) {
    __shared__ unsigned As[32][PADW];
    __shared__ unsigned Bs[32][PADW];
    __shared__ float s_sum[128], s_sq[128];
    const int K = DH;
    const float* A = g_z;

    int tid = threadIdx.x;
    int wid = tid >> 5, lane = tid & 31;
    int g = lane >> 2, tig = lane & 3;
    int warp_m = wid & 1, warp_n = wid >> 1;
    int brow = blockIdx.y * 128, bcol = blockIdx.x * 128;

    if (tid < 128) { s_sum[tid] = 0.f; s_sq[tid] = 0.f; }

    float acc[4][4][4];
#pragma unroll
    for (int mt = 0; mt < 4; mt++)
#pragma unroll
        for (int nt = 0; nt < 4; nt++)
#pragma unroll
            for (int r = 0; r < 4; r++) acc[mt][nt][r] = 0.f;

    for (int k0 = 0; k0 < K; k0 += 32) {
#pragma unroll
        for (int l = 0; l < 4; l++) {
            int s = tid + l * 256;
            int m = s >> 3, kq = s & 7;
            float4 v = make_float4(0.f, 0.f, 0.f, 0.f);
            if (brow + m < M)
                v = *(const float4*)(A + (size_t)(brow + m) * K + k0 + kq * 4);
            As[kq * 4 + 0][m] = f2tf32(v.x);
            As[kq * 4 + 1][m] = f2tf32(v.y);
            As[kq * 4 + 2][m] = f2tf32(v.z);
            As[kq * 4 + 3][m] = f2tf32(v.w);
        }
#pragma unroll
        for (int l = 0; l < 4; l++) {
            int s = tid + l * 256;
            int k = s >> 5, nq = s & 31;
            float4 v = *(const float4*)(B + (size_t)(k0 + k) * DH + bcol + nq * 4);
            Bs[k][nq * 4 + 0] = f2tf32(v.x);
            Bs[k][nq * 4 + 1] = f2tf32(v.y);
            Bs[k][nq * 4 + 2] = f2tf32(v.z);
            Bs[k][nq * 4 + 3] = f2tf32(v.w);
        }
        __syncthreads();
#pragma unroll
        for (int kk = 0; kk < 32; kk += 8) {
            unsigned af[4][4], bf[4][2];
#pragma unroll
            for (int mt = 0; mt < 4; mt++) {
                int mb = warp_m * 64 + mt * 16 + g;
                af[mt][0] = As[kk + tig    ][mb];
                af[mt][1] = As[kk + tig    ][mb + 8];
                af[mt][2] = As[kk + tig + 4][mb];
                af[mt][3] = As[kk + tig + 4][mb + 8];
            }
#pragma unroll
            for (int nt = 0; nt < 4; nt++) {
                int nb = warp_n * 32 + nt * 8 + g;
                bf[nt][0] = Bs[kk + tig    ][nb];
                bf[nt][1] = Bs[kk + tig + 4][nb];
            }
#pragma unroll
            for (int mt = 0; mt < 4; mt++)
#pragma unroll
                for (int nt = 0; nt < 4; nt++)
                    mma_tf32(acc[mt][nt], af[mt], bf[nt]);
        }
        __syncthreads();
    }

    // epilogue: g=sigmoid(acc+bg); out=relu(xl+g*(z-xl)); BN partial sums
    float csum[4][2], csq[4][2];
#pragma unroll
    for (int nt = 0; nt < 4; nt++) {
        csum[nt][0] = 0.f; csum[nt][1] = 0.f;
        csq [nt][0] = 0.f; csq [nt][1] = 0.f;
    }

#pragma unroll
    for (int mt = 0; mt < 4; mt++) {
#pragma unroll
        for (int half = 0; half < 2; half++) {
            int row = brow + warp_m * 64 + mt * 16 + g + half * 8;
            if (row >= M) continue;
#pragma unroll
            for (int nt = 0; nt < 4; nt++) {
                int col = bcol + warp_n * 32 + nt * 8 + 2 * tig;
                const float* zp = g_z  + (size_t)row * DH + col;
                const float* xp = g_xl + (size_t)row * DH + col;
                float*       op = OUT  + (size_t)row * DH + col;
                float2 zv = *(const float2*)zp;
                float2 xv = *(const float2*)xp;
#pragma unroll
                for (int c = 0; c < 2; c++) {
                    float gp = acc[mt][nt][half * 2 + c] + bgate[col + c];
                    float gg = 1.f / (1.f + expf(-gp));
                    float zz = c ? zv.y : zv.x;
                    float xx = c ? xv.y : xv.x;
                    float o = fmaf(gg, zz - xx, xx);
                    o = fmaxf(o, 0.f);
                    op[c] = o;
                    csum[nt][c] += o;
                    csq [nt][c] += o * o;
                }
            }
        }
    }
#pragma unroll
    for (int nt = 0; nt < 4; nt++) {
        int cl = warp_n * 32 + nt * 8 + 2 * tig;
        atomicAdd(&s_sum[cl],     csum[nt][0]);
        atomicAdd(&s_sum[cl + 1], csum[nt][1]);
        atomicAdd(&s_sq [cl],     csq [nt][0]);
        atomicAdd(&s_sq [cl + 1], csq [nt][1]);
    }
    __syncthreads();
    if (tid < 128) {
        atomicAdd(&g_bnsum[bcol + tid], s_sum[tid]);
        atomicAdd(&g_bnsq [bcol + tid], s_sq [tid]);
    }
}

// ---------------- BN finalize ----------------------------------------------
__global__ void k_bnstats(const float* __restrict__ gamma,
                          const float* __restrict__ beta, int N) {
    int c = threadIdx.x;
    if (c < DH) {
        float invn = 1.0f / (float)N;
        float mu  = g_bnsum[c] * invn;
        float var = g_bnsq[c] * invn - mu * mu;
        float sc  = gamma[c] * rsqrtf(var + BN_EPS);
        g_bnscale[c] = sc;
        g_bnshift[c] = beta[c] - mu * sc;
    }
}

__global__ void k_norm(float* __restrict__ OUT, int N) {
    int i = blockIdx.x * blockDim.x + threadIdx.x;
    int total = N * (DH / 4);
    if (i >= total) return;
    int c4 = i & 63;
    float4 sc = ((const float4*)g_bnscale)[c4];
    float4 sh = ((const float4*)g_bnshift)[c4];
    float4 v = ((float4*)OUT)[i];
    v.x = fmaf(v.x, sc.x, sh.x);
    v.y = fmaf(v.y, sc.y, sh.y);
    v.z = fmaf(v.z, sc.z, sh.z);
    v.w = fmaf(v.w, sc.w, sh.w);
    ((float4*)OUT)[i] = v;
}

// ---------------- launch ----------------------------------------------------
extern "C" void kernel_launch(void* const* d_in, const int* in_sizes, int n_in,
                              void* d_out, int out_size) {
    const float* xs     = (const float*)d_in[0];
    const void*  edges  =               d_in[1];
    const float* W_gcn  = (const float*)d_in[2];
    const float* b_gcn  = (const float*)d_in[3];
    const float* W_lin  = (const float*)d_in[4];
    const float* b_lin  = (const float*)d_in[5];
    const float* W_gate = (const float*)d_in[6];
    const float* b_gate = (const float*)d_in[7];
    const float* gamma  = (const float*)d_in[8];
    const float* beta   = (const float*)d_in[9];
    float* out = (float*)d_out;

    int N = in_sizes[0] / DIN;     // 50000
    int E = in_sizes[1] / 2;       // 800000

    int nwords = 2048;
    if (2 * E < nwords) nwords = 2 * E;

    int nb = (N + SCAN_CHUNK - 1) / SCAN_CHUNK;
    if (nb > 64) nb = 64;          // g_blocksum capacity guard (N<=65536 here)

    k_detect<<<1, 32>>>((const int*)edges, nwords);
    k_init<<<(N + 255) / 256, 256>>>(N);
    k_count<<<(E + 255) / 256, 256>>>(edges, E);
    k_scan_p1<<<nb, SCAN_CHUNK>>>(N);
    k_scan_p2<<<1, 32>>>(nb, N);
    k_scan_p3<<<nb, SCAN_CHUNK>>>(N);
    k_fillcsr<<<(E + 255) / 256, 256>>>(edges, E);

    k_gatherx<<<(N + 7) / 8, 256>>>(xs, N);

    dim3 g2(2, (N + 127) / 128, 2);
    k_gemm_tf32<<<g2, 256>>>(xs, W_gcn, W_lin, b_gcn, b_lin, N);  // -> g_z, g_xl

    dim3 g1(2, (N + 127) / 128);
    k_gate_tf32<<<g1, 256>>>(W_gate, b_gate, out, N);

    k_bnstats<<<1, 256>>>(gamma, beta, N);
    k_norm<<<(N * (DH / 4) + 255) / 256, 256>>>(out, N);
}